// round 1
// baseline (speedup 1.0000x reference)
#include <cuda_runtime.h>
#include <math.h>

#define Bt   16
#define Cc   384
#define Nn   1024
#define NHh  8
#define HDd  48
#define MIDm 384
#define HIDh 1536

// ---------------- scratch (device globals; no allocations allowed) ----------
__device__ float g_h1 [Bt * Cc   * Nn];
__device__ float g_q  [Bt * MIDm * Nn];
__device__ float g_kv [Bt * 2 * MIDm * Nn];
__device__ float g_att[Bt * MIDm * Nn];
__device__ float g_x2 [Bt * Cc   * Nn];
__device__ float g_h2 [Bt * Cc   * Nn];
__device__ float g_hid[Bt * HIDh * Nn];

// ---------------- channel LayerNorm over NCHW (per (b, spatial)) ------------
// grid (Nn/32, Bt), block (32, 8)
__global__ void ln_kernel(const float* __restrict__ X,
                          const float* __restrict__ gam,
                          const float* __restrict__ bet,
                          float* __restrict__ Y) {
    __shared__ float ss[8][32], sq[8][32], sm[32], sr[32];
    int b  = blockIdx.y;
    int n  = blockIdx.x * 32 + threadIdx.x;
    int ty = threadIdx.y;
    const float* xb = X + (size_t)b * Cc * Nn + n;
    float s = 0.f, q = 0.f;
    for (int c = ty; c < Cc; c += 8) {
        float v = xb[(size_t)c * Nn];
        s += v; q += v * v;
    }
    ss[ty][threadIdx.x] = s;
    sq[ty][threadIdx.x] = q;
    __syncthreads();
    if (ty == 0) {
        float S = 0.f, Q = 0.f;
        #pragma unroll
        for (int r = 0; r < 8; r++) { S += ss[r][threadIdx.x]; Q += sq[r][threadIdx.x]; }
        float mean = S * (1.0f / Cc);
        float var  = Q * (1.0f / Cc) - mean * mean;
        sm[threadIdx.x] = mean;
        sr[threadIdx.x] = rsqrtf(var + 1e-5f);
    }
    __syncthreads();
    float mean = sm[threadIdx.x];
    float rstd = sr[threadIdx.x];
    float* yb = Y + (size_t)b * Cc * Nn + n;
    for (int c = ty; c < Cc; c += 8) {
        float v = xb[(size_t)c * Nn];
        yb[(size_t)c * Nn] = (v - mean) * rstd * gam[c] + bet[c];
    }
}

// ---------------- generic fp32 GEMM: Y[b,o,n] = sum_c W[o,c]*X[b,c,n] -------
// tile 128(o) x 64(n), K-step 16; block (16,16), each thread 8x4.
// act: 0 = none, 1 = exact GELU. res: optional residual [B,O,N].
__global__ void __launch_bounds__(256)
gemm_kernel(const float* __restrict__ X, const float* __restrict__ Wm,
            const float* __restrict__ bias, const float* __restrict__ res,
            float* __restrict__ Y, int O, int Cin, int act) {
    __shared__ float Ws[16][132];   // [k][o], padded (132*4B, 16B-aligned rows)
    __shared__ float Xs[16][64];    // [k][n]
    int b  = blockIdx.z;
    int o0 = blockIdx.y * 128;
    int n0 = blockIdx.x * 64;
    int tx = threadIdx.x, ty = threadIdx.y;
    int tid = ty * 16 + tx;
    const float* Xb = X + (size_t)b * Cin * Nn;

    float acc[8][4];
    #pragma unroll
    for (int i = 0; i < 8; i++)
        #pragma unroll
        for (int j = 0; j < 4; j++) acc[i][j] = 0.f;

    for (int k0 = 0; k0 < Cin; k0 += 16) {
        #pragma unroll
        for (int r = 0; r < 8; r++) {          // 128x16 W tile
            int idx = tid + r * 256;
            int kk = idx & 15, oo = idx >> 4;
            Ws[kk][oo] = Wm[(size_t)(o0 + oo) * Cin + (k0 + kk)];
        }
        #pragma unroll
        for (int r = 0; r < 4; r++) {          // 16x64 X tile
            int idx = tid + r * 256;
            int nn = idx & 63, kk = idx >> 6;
            Xs[kk][nn] = Xb[(size_t)(k0 + kk) * Nn + (n0 + nn)];
        }
        __syncthreads();
        #pragma unroll
        for (int k = 0; k < 16; k++) {
            float4 w0 = *(const float4*)&Ws[k][ty * 8];
            float4 w1 = *(const float4*)&Ws[k][ty * 8 + 4];
            float4 xv = *(const float4*)&Xs[k][tx * 4];
            float wa[8] = {w0.x, w0.y, w0.z, w0.w, w1.x, w1.y, w1.z, w1.w};
            float xa[4] = {xv.x, xv.y, xv.z, xv.w};
            #pragma unroll
            for (int i = 0; i < 8; i++)
                #pragma unroll
                for (int j = 0; j < 4; j++) acc[i][j] += wa[i] * xa[j];
        }
        __syncthreads();
    }

    #pragma unroll
    for (int i = 0; i < 8; i++) {
        int o = o0 + ty * 8 + i;
        float bv = bias[o];
        float tmp[4];
        #pragma unroll
        for (int j = 0; j < 4; j++) {
            float t = acc[i][j] + bv;
            if (act) t = 0.5f * t * (1.0f + erff(t * 0.70710678118654752f));
            tmp[j] = t;
        }
        size_t off = ((size_t)b * O + o) * Nn + n0 + tx * 4;
        if (res) {
            float4 rv = *(const float4*)&res[off];
            tmp[0] += rv.x; tmp[1] += rv.y; tmp[2] += rv.z; tmp[3] += rv.w;
        }
        float4 v = make_float4(tmp[0], tmp[1], tmp[2], tmp[3]);
        *(float4*)&Y[off] = v;
    }
}

// ---------------- flash attention per (b, h): 64 queries x 32-key tiles -----
// grid (Nn/64, NHh, Bt), block (16,16)
__global__ void __launch_bounds__(256)
flash_kernel(const float* __restrict__ qg, const float* __restrict__ kvg,
             const float* __restrict__ rpb, const int* __restrict__ ridx,
             float* __restrict__ outg) {
    __shared__ float Qs[48][64];     // [d][i]
    __shared__ float Ks[48][33];     // [d][j]
    __shared__ float Vs[48][33];     // [d][j]
    __shared__ float Ps[64][33];     // [i][j]
    __shared__ float m_sh[64], l_sh[64], a_sh[64];

    int b = blockIdx.z, h = blockIdx.y, n0 = blockIdx.x * 64;
    int tx = threadIdx.x, ty = threadIdx.y;
    int tid = ty * 16 + tx;

    const float* Qb = qg  + ((size_t)b * MIDm + h * HDd) * Nn;
    const float* Kb = kvg + ((size_t)b * 2 * MIDm + h * HDd) * Nn;
    const float* Vb = kvg + ((size_t)b * 2 * MIDm + MIDm + h * HDd) * Nn;

    for (int idx = tid; idx < 48 * 64; idx += 256) {
        int d = idx >> 6, i = idx & 63;
        Qs[d][i] = Qb[(size_t)d * Nn + n0 + i];
    }
    if (tid < 64) { m_sh[tid] = -1e30f; l_sh[tid] = 0.f; }

    float o[4][3];
    #pragma unroll
    for (int i = 0; i < 4; i++)
        #pragma unroll
        for (int d = 0; d < 3; d++) o[i][d] = 0.f;

    const float scale = 0.14433756729740645f;  // 48^{-1/2}

    for (int t = 0; t < 32; t++) {
        int m0 = t * 32;
        __syncthreads();                       // protect Ks/Vs/Ps reuse
        for (int idx = tid; idx < 48 * 32; idx += 256) {
            int d = idx >> 5, j = idx & 31;
            Ks[d][j] = Kb[(size_t)d * Nn + m0 + j];
            Vs[d][j] = Vb[(size_t)d * Nn + m0 + j];
        }
        __syncthreads();

        float s[4][2];
        #pragma unroll
        for (int i = 0; i < 4; i++) { s[i][0] = 0.f; s[i][1] = 0.f; }
        #pragma unroll 8
        for (int d = 0; d < 48; d++) {
            float4 q4 = *(const float4*)&Qs[d][ty * 4];
            float k0v = Ks[d][tx * 2], k1v = Ks[d][tx * 2 + 1];
            s[0][0] += q4.x * k0v; s[0][1] += q4.x * k1v;
            s[1][0] += q4.y * k0v; s[1][1] += q4.y * k1v;
            s[2][0] += q4.z * k0v; s[2][1] += q4.z * k1v;
            s[3][0] += q4.w * k0v; s[3][1] += q4.w * k1v;
        }

        // scale + relative-position bias (gather; rel_index resident in L2)
        #pragma unroll
        for (int i = 0; i < 4; i++) {
            int n = n0 + ty * 4 + i;
            const int* rrow = ridx + (size_t)n * Nn + m0 + tx * 2;
            #pragma unroll
            for (int j = 0; j < 2; j++) {
                int r = rrow[j];
                s[i][j] = s[i][j] * scale + rpb[r * NHh + h];
            }
        }

        // online softmax (row group = 16 lanes of one warp)
        #pragma unroll
        for (int i = 0; i < 4; i++) {
            int row = ty * 4 + i;
            float rm = fmaxf(s[i][0], s[i][1]);
            #pragma unroll
            for (int off = 1; off < 16; off <<= 1)
                rm = fmaxf(rm, __shfl_xor_sync(0xffffffffu, rm, off));
            float mo = m_sh[row];
            float mn = fmaxf(mo, rm);
            float p0 = __expf(s[i][0] - mn);
            float p1 = __expf(s[i][1] - mn);
            float rs = p0 + p1;
            #pragma unroll
            for (int off = 1; off < 16; off <<= 1)
                rs += __shfl_xor_sync(0xffffffffu, rs, off);
            if (tx == 0) {
                float al = __expf(mo - mn);
                a_sh[row] = al;
                l_sh[row] = l_sh[row] * al + rs;
                m_sh[row] = mn;
            }
            Ps[row][tx * 2]     = p0;
            Ps[row][tx * 2 + 1] = p1;
        }
        __syncthreads();

        float al[4];
        #pragma unroll
        for (int i = 0; i < 4; i++) al[i] = a_sh[ty * 4 + i];
        #pragma unroll
        for (int i = 0; i < 4; i++)
            #pragma unroll
            for (int d = 0; d < 3; d++) o[i][d] *= al[i];

        #pragma unroll 4
        for (int j = 0; j < 32; j++) {
            float pv[4], vv[3];
            #pragma unroll
            for (int i = 0; i < 4; i++) pv[i] = Ps[ty * 4 + i][j];
            #pragma unroll
            for (int d = 0; d < 3; d++) vv[d] = Vs[tx * 3 + d][j];
            #pragma unroll
            for (int i = 0; i < 4; i++)
                #pragma unroll
                for (int d = 0; d < 3; d++) o[i][d] += pv[i] * vv[d];
        }
    }

    // epilogue: normalize and write [MID, N] layout
    #pragma unroll
    for (int i = 0; i < 4; i++) {
        float inv = 1.0f / l_sh[ty * 4 + i];
        int n = n0 + ty * 4 + i;
        #pragma unroll
        for (int d = 0; d < 3; d++) {
            outg[((size_t)b * MIDm + h * HDd + tx * 3 + d) * Nn + n] = o[i][d] * inv;
        }
    }
}

// ---------------- launch --------------------------------------------------
extern "C" void kernel_launch(void* const* d_in, const int* in_sizes, int n_in,
                              void* d_out, int out_size) {
    const float* x     = (const float*)d_in[0];
    const float* rpb   = (const float*)d_in[1];
    const int*   ridx  = (const int*)  d_in[2];
    const float* ln1g  = (const float*)d_in[3];
    const float* ln1b  = (const float*)d_in[4];
    const float* ln2g  = (const float*)d_in[5];
    const float* ln2b  = (const float*)d_in[6];
    const float* wq    = (const float*)d_in[7];
    const float* bq    = (const float*)d_in[8];
    const float* wkv   = (const float*)d_in[9];
    const float* bkv   = (const float*)d_in[10];
    const float* wproj = (const float*)d_in[11];
    const float* bproj = (const float*)d_in[12];
    const float* w1    = (const float*)d_in[13];
    const float* b1    = (const float*)d_in[14];
    const float* w2    = (const float*)d_in[15];
    const float* b2    = (const float*)d_in[16];
    float* out = (float*)d_out;

    float *h1, *q, *kv, *att, *x2, *h2, *hid;
    cudaGetSymbolAddress((void**)&h1,  g_h1);
    cudaGetSymbolAddress((void**)&q,   g_q);
    cudaGetSymbolAddress((void**)&kv,  g_kv);
    cudaGetSymbolAddress((void**)&att, g_att);
    cudaGetSymbolAddress((void**)&x2,  g_x2);
    cudaGetSymbolAddress((void**)&h2,  g_h2);
    cudaGetSymbolAddress((void**)&hid, g_hid);

    dim3 lnGrid(Nn / 32, Bt), lnBlk(32, 8);
    dim3 gBlk(16, 16);

    // LN1
    ln_kernel<<<lnGrid, lnBlk>>>(x, ln1g, ln1b, h1);
    // Q / KV projections
    gemm_kernel<<<dim3(Nn / 64, MIDm / 128, Bt), gBlk>>>(h1, wq, bq, nullptr, q, MIDm, Cc, 0);
    gemm_kernel<<<dim3(Nn / 64, 2 * MIDm / 128, Bt), gBlk>>>(h1, wkv, bkv, nullptr, kv, 2 * MIDm, Cc, 0);
    // attention
    flash_kernel<<<dim3(Nn / 64, NHh, Bt), gBlk>>>(q, kv, rpb, ridx, att);
    // output projection + residual
    gemm_kernel<<<dim3(Nn / 64, Cc / 128, Bt), gBlk>>>(att, wproj, bproj, x, x2, Cc, MIDm, 0);
    // LN2
    ln_kernel<<<lnGrid, lnBlk>>>(x2, ln2g, ln2b, h2);
    // MLP
    gemm_kernel<<<dim3(Nn / 64, HIDh / 128, Bt), gBlk>>>(h2, w1, b1, nullptr, hid, HIDh, Cc, 1);
    gemm_kernel<<<dim3(Nn / 64, Cc / 128, Bt), gBlk>>>(hid, w2, b2, x2, out, Cc, HIDh, 0);
}

// round 2
// speedup vs baseline: 1.6282x; 1.6282x over previous
#include <cuda_runtime.h>
#include <math.h>
#include <stdint.h>

#define Bt   16
#define Cc   384
#define Nn   1024
#define NHh  8
#define HDd  48
#define MIDm 384
#define HIDh 1536

// ---------------- scratch (device globals; no allocations allowed) ----------
__device__ float g_h1 [Bt * Cc   * Nn];
__device__ float g_q  [Bt * MIDm * Nn];
__device__ float g_kv [Bt * 2 * MIDm * Nn];
__device__ float g_att[Bt * MIDm * Nn];
__device__ float g_x2 [Bt * Cc   * Nn];
__device__ float g_h2 [Bt * Cc   * Nn];
__device__ float g_hid[Bt * HIDh * Nn];

__device__ __forceinline__ uint32_t f2tf32(float f) {
    uint32_t u;
    asm("cvt.rna.tf32.f32 %0, %1;" : "=r"(u) : "f"(f));
    return u;
}

// ---------------- channel LayerNorm over NCHW (per (b, spatial)) ------------
// grid (Nn/32, Bt), block (32, 8)
__global__ void ln_kernel(const float* __restrict__ X,
                          const float* __restrict__ gam,
                          const float* __restrict__ bet,
                          float* __restrict__ Y) {
    __shared__ float ss[8][32], sq[8][32], sm[32], sr[32];
    int b  = blockIdx.y;
    int n  = blockIdx.x * 32 + threadIdx.x;
    int ty = threadIdx.y;
    const float* xb = X + (size_t)b * Cc * Nn + n;
    float s = 0.f, q = 0.f;
    for (int c = ty; c < Cc; c += 8) {
        float v = xb[(size_t)c * Nn];
        s += v; q += v * v;
    }
    ss[ty][threadIdx.x] = s;
    sq[ty][threadIdx.x] = q;
    __syncthreads();
    if (ty == 0) {
        float S = 0.f, Q = 0.f;
        #pragma unroll
        for (int r = 0; r < 8; r++) { S += ss[r][threadIdx.x]; Q += sq[r][threadIdx.x]; }
        float mean = S * (1.0f / Cc);
        float var  = Q * (1.0f / Cc) - mean * mean;
        sm[threadIdx.x] = mean;
        sr[threadIdx.x] = rsqrtf(var + 1e-5f);
    }
    __syncthreads();
    float mean = sm[threadIdx.x];
    float rstd = sr[threadIdx.x];
    float* yb = Y + (size_t)b * Cc * Nn + n;
    for (int c = ty; c < Cc; c += 8) {
        float v = xb[(size_t)c * Nn];
        yb[(size_t)c * Nn] = (v - mean) * rstd * gam[c] + bet[c];
    }
}

// ---------------- TF32 tensor-core GEMM: Y[b,o,n] = sum_c W[o,c]*X[b,c,n] ---
// Block tile 128(o) x 128(n), K-step 32. 8 warps: 2(o) x 4(n), each 64x32.
// Per warp: 4x4 grid of m16n8k8 tf32 mma. Fused bias / GELU / residual.
__global__ void __launch_bounds__(256)
gemm_tf32(const float* __restrict__ X, const float* __restrict__ Wm,
          const float* __restrict__ bias, const float* __restrict__ res,
          float* __restrict__ Y, int O, int Cin, int act) {
    __shared__ uint32_t Ws[128][36];   // [o][k] padded: frag loads conflict-free
    __shared__ uint32_t Xs[32][132];   // [k][n] padded

    int b  = blockIdx.z;
    int o0 = blockIdx.y * 128;
    int n0 = blockIdx.x * 128;
    int tid  = threadIdx.x;
    int lane = tid & 31;
    int warp = tid >> 5;
    int wO = (warp >> 2) * 64;
    int wN = (warp & 3) * 32;
    const float* Xb = X + (size_t)b * Cin * Nn;

    float acc[4][4][4];
    #pragma unroll
    for (int m = 0; m < 4; m++)
        #pragma unroll
        for (int n = 0; n < 4; n++)
            #pragma unroll
            for (int r = 0; r < 4; r++) acc[m][n][r] = 0.f;

    for (int k0 = 0; k0 < Cin; k0 += 32) {
        // W tile: 128 rows x 32 k (float4 over k, coalesced within row)
        #pragma unroll
        for (int r = 0; r < 4; r++) {
            int o  = (tid >> 3) + r * 32;
            int kk = (tid & 7) * 4;
            float4 w = *(const float4*)&Wm[(size_t)(o0 + o) * Cin + k0 + kk];
            uint4 u = make_uint4(f2tf32(w.x), f2tf32(w.y), f2tf32(w.z), f2tf32(w.w));
            *(uint4*)&Ws[o][kk] = u;
        }
        // X tile: 32 k-rows x 128 n (float4 over n, coalesced)
        #pragma unroll
        for (int r = 0; r < 4; r++) {
            int kk = (tid >> 5) + r * 8;
            int nn = (tid & 31) * 4;
            float4 xv = *(const float4*)&Xb[(size_t)(k0 + kk) * Nn + n0 + nn];
            uint4 u = make_uint4(f2tf32(xv.x), f2tf32(xv.y), f2tf32(xv.z), f2tf32(xv.w));
            *(uint4*)&Xs[kk][nn] = u;
        }
        __syncthreads();

        #pragma unroll
        for (int ks = 0; ks < 4; ks++) {
            uint32_t af[4][4], bf[4][2];
            int rA = wO + (lane >> 2);
            int cA = ks * 8 + (lane & 3);
            #pragma unroll
            for (int m = 0; m < 4; m++) {
                int rr = rA + m * 16;
                af[m][0] = Ws[rr][cA];
                af[m][1] = Ws[rr + 8][cA];
                af[m][2] = Ws[rr][cA + 4];
                af[m][3] = Ws[rr + 8][cA + 4];
            }
            int kB = ks * 8 + (lane & 3);
            int nB = wN + (lane >> 2);
            #pragma unroll
            for (int n = 0; n < 4; n++) {
                bf[n][0] = Xs[kB][nB + n * 8];
                bf[n][1] = Xs[kB + 4][nB + n * 8];
            }
            #pragma unroll
            for (int m = 0; m < 4; m++)
                #pragma unroll
                for (int n = 0; n < 4; n++) {
                    asm volatile(
                        "mma.sync.aligned.m16n8k8.row.col.f32.tf32.tf32.f32 "
                        "{%0,%1,%2,%3}, {%4,%5,%6,%7}, {%8,%9}, {%0,%1,%2,%3};\n"
                        : "+f"(acc[m][n][0]), "+f"(acc[m][n][1]),
                          "+f"(acc[m][n][2]), "+f"(acc[m][n][3])
                        : "r"(af[m][0]), "r"(af[m][1]), "r"(af[m][2]), "r"(af[m][3]),
                          "r"(bf[n][0]), "r"(bf[n][1]));
                }
        }
        __syncthreads();
    }

    // epilogue: bias (+GELU) (+residual), write [B,O,N]
    #pragma unroll
    for (int m = 0; m < 4; m++) {
        int row = o0 + wO + m * 16 + (lane >> 2);
        float bv0 = bias[row];
        float bv1 = bias[row + 8];
        #pragma unroll
        for (int n = 0; n < 4; n++) {
            int col = n0 + wN + n * 8 + 2 * (lane & 3);
            float t0 = acc[m][n][0] + bv0;
            float t1 = acc[m][n][1] + bv0;
            float t2 = acc[m][n][2] + bv1;
            float t3 = acc[m][n][3] + bv1;
            if (act) {
                t0 = 0.5f * t0 * (1.0f + erff(t0 * 0.70710678118654752f));
                t1 = 0.5f * t1 * (1.0f + erff(t1 * 0.70710678118654752f));
                t2 = 0.5f * t2 * (1.0f + erff(t2 * 0.70710678118654752f));
                t3 = 0.5f * t3 * (1.0f + erff(t3 * 0.70710678118654752f));
            }
            size_t off0 = ((size_t)b * O + row) * Nn + col;
            size_t off1 = ((size_t)b * O + row + 8) * Nn + col;
            if (res) {
                float2 r0 = *(const float2*)&res[off0];
                float2 r1 = *(const float2*)&res[off1];
                t0 += r0.x; t1 += r0.y; t2 += r1.x; t3 += r1.y;
            }
            *(float2*)&Y[off0] = make_float2(t0, t1);
            *(float2*)&Y[off1] = make_float2(t2, t3);
        }
    }
}

// ---------------- flash attention per (b, h): 64 queries x 32-key tiles -----
// grid (Nn/64, NHh, Bt), block (16,16)
__global__ void __launch_bounds__(256)
flash_kernel(const float* __restrict__ qg, const float* __restrict__ kvg,
             const float* __restrict__ rpb, const int* __restrict__ ridx,
             float* __restrict__ outg) {
    __shared__ float Qs[48][64];     // [d][i]
    __shared__ float Ks[48][33];     // [d][j]
    __shared__ float Vs[48][33];     // [d][j]
    __shared__ float Ps[64][33];     // [i][j]
    __shared__ float m_sh[64], l_sh[64], a_sh[64];

    int b = blockIdx.z, h = blockIdx.y, n0 = blockIdx.x * 64;
    int tx = threadIdx.x, ty = threadIdx.y;
    int tid = ty * 16 + tx;

    const float* Qb = qg  + ((size_t)b * MIDm + h * HDd) * Nn;
    const float* Kb = kvg + ((size_t)b * 2 * MIDm + h * HDd) * Nn;
    const float* Vb = kvg + ((size_t)b * 2 * MIDm + MIDm + h * HDd) * Nn;

    for (int idx = tid; idx < 48 * 64; idx += 256) {
        int d = idx >> 6, i = idx & 63;
        Qs[d][i] = Qb[(size_t)d * Nn + n0 + i];
    }
    if (tid < 64) { m_sh[tid] = -1e30f; l_sh[tid] = 0.f; }

    float o[4][3];
    #pragma unroll
    for (int i = 0; i < 4; i++)
        #pragma unroll
        for (int d = 0; d < 3; d++) o[i][d] = 0.f;

    const float scale = 0.14433756729740645f;  // 48^{-1/2}

    for (int t = 0; t < 32; t++) {
        int m0 = t * 32;
        __syncthreads();                       // protect Ks/Vs/Ps reuse
        for (int idx = tid; idx < 48 * 32; idx += 256) {
            int d = idx >> 5, j = idx & 31;
            Ks[d][j] = Kb[(size_t)d * Nn + m0 + j];
            Vs[d][j] = Vb[(size_t)d * Nn + m0 + j];
        }
        __syncthreads();

        float s[4][2];
        #pragma unroll
        for (int i = 0; i < 4; i++) { s[i][0] = 0.f; s[i][1] = 0.f; }
        #pragma unroll 8
        for (int d = 0; d < 48; d++) {
            float4 q4 = *(const float4*)&Qs[d][ty * 4];
            float k0v = Ks[d][tx * 2], k1v = Ks[d][tx * 2 + 1];
            s[0][0] += q4.x * k0v; s[0][1] += q4.x * k1v;
            s[1][0] += q4.y * k0v; s[1][1] += q4.y * k1v;
            s[2][0] += q4.z * k0v; s[2][1] += q4.z * k1v;
            s[3][0] += q4.w * k0v; s[3][1] += q4.w * k1v;
        }

        // scale + relative-position bias (gather; rel_index resident in L2)
        #pragma unroll
        for (int i = 0; i < 4; i++) {
            int n = n0 + ty * 4 + i;
            const int* rrow = ridx + (size_t)n * Nn + m0 + tx * 2;
            #pragma unroll
            for (int j = 0; j < 2; j++) {
                int r = rrow[j];
                s[i][j] = s[i][j] * scale + rpb[r * NHh + h];
            }
        }

        // online softmax (row group = 16 lanes of one warp)
        #pragma unroll
        for (int i = 0; i < 4; i++) {
            int row = ty * 4 + i;
            float rm = fmaxf(s[i][0], s[i][1]);
            #pragma unroll
            for (int off = 1; off < 16; off <<= 1)
                rm = fmaxf(rm, __shfl_xor_sync(0xffffffffu, rm, off));
            float mo = m_sh[row];
            float mn = fmaxf(mo, rm);
            float p0 = __expf(s[i][0] - mn);
            float p1 = __expf(s[i][1] - mn);
            float rs = p0 + p1;
            #pragma unroll
            for (int off = 1; off < 16; off <<= 1)
                rs += __shfl_xor_sync(0xffffffffu, rs, off);
            if (tx == 0) {
                float al = __expf(mo - mn);
                a_sh[row] = al;
                l_sh[row] = l_sh[row] * al + rs;
                m_sh[row] = mn;
            }
            Ps[row][tx * 2]     = p0;
            Ps[row][tx * 2 + 1] = p1;
        }
        __syncthreads();

        float al[4];
        #pragma unroll
        for (int i = 0; i < 4; i++) al[i] = a_sh[ty * 4 + i];
        #pragma unroll
        for (int i = 0; i < 4; i++)
            #pragma unroll
            for (int d = 0; d < 3; d++) o[i][d] *= al[i];

        #pragma unroll 4
        for (int j = 0; j < 32; j++) {
            float pv[4], vv[3];
            #pragma unroll
            for (int i = 0; i < 4; i++) pv[i] = Ps[ty * 4 + i][j];
            #pragma unroll
            for (int d = 0; d < 3; d++) vv[d] = Vs[tx * 3 + d][j];
            #pragma unroll
            for (int i = 0; i < 4; i++)
                #pragma unroll
                for (int d = 0; d < 3; d++) o[i][d] += pv[i] * vv[d];
        }
    }

    // epilogue: normalize and write [MID, N] layout
    #pragma unroll
    for (int i = 0; i < 4; i++) {
        float inv = 1.0f / l_sh[ty * 4 + i];
        int n = n0 + ty * 4 + i;
        #pragma unroll
        for (int d = 0; d < 3; d++) {
            outg[((size_t)b * MIDm + h * HDd + tx * 3 + d) * Nn + n] = o[i][d] * inv;
        }
    }
}

// ---------------- launch --------------------------------------------------
extern "C" void kernel_launch(void* const* d_in, const int* in_sizes, int n_in,
                              void* d_out, int out_size) {
    const float* x     = (const float*)d_in[0];
    const float* rpb   = (const float*)d_in[1];
    const int*   ridx  = (const int*)  d_in[2];
    const float* ln1g  = (const float*)d_in[3];
    const float* ln1b  = (const float*)d_in[4];
    const float* ln2g  = (const float*)d_in[5];
    const float* ln2b  = (const float*)d_in[6];
    const float* wq    = (const float*)d_in[7];
    const float* bq    = (const float*)d_in[8];
    const float* wkv   = (const float*)d_in[9];
    const float* bkv   = (const float*)d_in[10];
    const float* wproj = (const float*)d_in[11];
    const float* bproj = (const float*)d_in[12];
    const float* w1    = (const float*)d_in[13];
    const float* b1    = (const float*)d_in[14];
    const float* w2    = (const float*)d_in[15];
    const float* b2    = (const float*)d_in[16];
    float* out = (float*)d_out;

    float *h1, *q, *kv, *att, *x2, *h2, *hid;
    cudaGetSymbolAddress((void**)&h1,  g_h1);
    cudaGetSymbolAddress((void**)&q,   g_q);
    cudaGetSymbolAddress((void**)&kv,  g_kv);
    cudaGetSymbolAddress((void**)&att, g_att);
    cudaGetSymbolAddress((void**)&x2,  g_x2);
    cudaGetSymbolAddress((void**)&h2,  g_h2);
    cudaGetSymbolAddress((void**)&hid, g_hid);

    dim3 lnGrid(Nn / 32, Bt), lnBlk(32, 8);

    // LN1
    ln_kernel<<<lnGrid, lnBlk>>>(x, ln1g, ln1b, h1);
    // Q / KV projections (tensor cores, tf32)
    gemm_tf32<<<dim3(Nn / 128, MIDm / 128, Bt), 256>>>(h1, wq, bq, nullptr, q, MIDm, Cc, 0);
    gemm_tf32<<<dim3(Nn / 128, 2 * MIDm / 128, Bt), 256>>>(h1, wkv, bkv, nullptr, kv, 2 * MIDm, Cc, 0);
    // attention
    flash_kernel<<<dim3(Nn / 64, NHh, Bt), dim3(16, 16)>>>(q, kv, rpb, ridx, att);
    // output projection + residual
    gemm_tf32<<<dim3(Nn / 128, Cc / 128, Bt), 256>>>(att, wproj, bproj, x, x2, Cc, MIDm, 0);
    // LN2
    ln_kernel<<<lnGrid, lnBlk>>>(x2, ln2g, ln2b, h2);
    // MLP
    gemm_tf32<<<dim3(Nn / 128, HIDh / 128, Bt), 256>>>(h2, w1, b1, nullptr, hid, HIDh, Cc, 1);
    gemm_tf32<<<dim3(Nn / 128, Cc / 128, Bt), 256>>>(hid, w2, b2, x2, out, Cc, HIDh, 0);
}

// round 3
// speedup vs baseline: 2.7098x; 1.6643x over previous
#include <cuda_runtime.h>
#include <math.h>
#include <stdint.h>

#define Bt   16
#define Cc   384
#define Nn   1024
#define NHh  8
#define HDd  48
#define MIDm 384
#define HIDh 1536

// ---------------- scratch (device globals; no allocations allowed) ----------
__device__ float g_h1  [Bt * Cc   * Nn];
__device__ float g_q   [Bt * MIDm * Nn];
__device__ float g_kv  [Bt * 2 * MIDm * Nn];
__device__ float g_att [Bt * MIDm * Nn];
__device__ float g_x2  [Bt * Cc   * Nn];
__device__ float g_h2  [Bt * Cc   * Nn];
__device__ float g_hid [Bt * HIDh * Nn];
__device__ float g_bias[NHh * Nn * Nn];   // 32 MB precomputed softmax bias (*log2e)

__device__ __forceinline__ uint32_t f2tf32(float f) {
    uint32_t u;
    asm("cvt.rna.tf32.f32 %0, %1;" : "=r"(u) : "f"(f));
    return u;
}

// ---------------- bias precompute: gbias[h][n][m] = rpb[ridx[n][m]][h]*log2e -
__global__ void bias_pre(const float* __restrict__ rpb, const int* __restrict__ ridx,
                         float* __restrict__ gb) {
    int idx = blockIdx.x * 256 + threadIdx.x;          // over Nn*Nn
    int r = ridx[idx];
    float4 t0 = *(const float4*)&rpb[r * NHh];
    float4 t1 = *(const float4*)&rpb[r * NHh + 4];
    const float L2E = 1.4426950408889634f;
    gb[0 * Nn * Nn + idx] = t0.x * L2E;
    gb[1 * Nn * Nn + idx] = t0.y * L2E;
    gb[2 * Nn * Nn + idx] = t0.z * L2E;
    gb[3 * Nn * Nn + idx] = t0.w * L2E;
    gb[4 * Nn * Nn + idx] = t1.x * L2E;
    gb[5 * Nn * Nn + idx] = t1.y * L2E;
    gb[6 * Nn * Nn + idx] = t1.z * L2E;
    gb[7 * Nn * Nn + idx] = t1.w * L2E;
}

// ---------------- channel LayerNorm over NCHW (per (b, spatial)) ------------
__global__ void ln_kernel(const float* __restrict__ X,
                          const float* __restrict__ gam,
                          const float* __restrict__ bet,
                          float* __restrict__ Y) {
    __shared__ float ss[8][32], sq[8][32], sm[32], sr[32];
    int b  = blockIdx.y;
    int n  = blockIdx.x * 32 + threadIdx.x;
    int ty = threadIdx.y;
    const float* xb = X + (size_t)b * Cc * Nn + n;
    float s = 0.f, q = 0.f;
    for (int c = ty; c < Cc; c += 8) {
        float v = xb[(size_t)c * Nn];
        s += v; q += v * v;
    }
    ss[ty][threadIdx.x] = s;
    sq[ty][threadIdx.x] = q;
    __syncthreads();
    if (ty == 0) {
        float S = 0.f, Q = 0.f;
        #pragma unroll
        for (int r = 0; r < 8; r++) { S += ss[r][threadIdx.x]; Q += sq[r][threadIdx.x]; }
        float mean = S * (1.0f / Cc);
        float var  = Q * (1.0f / Cc) - mean * mean;
        sm[threadIdx.x] = mean;
        sr[threadIdx.x] = rsqrtf(var + 1e-5f);
    }
    __syncthreads();
    float mean = sm[threadIdx.x];
    float rstd = sr[threadIdx.x];
    float* yb = Y + (size_t)b * Cc * Nn + n;
    for (int c = ty; c < Cc; c += 8) {
        float v = xb[(size_t)c * Nn];
        yb[(size_t)c * Nn] = (v - mean) * rstd * gam[c] + bet[c];
    }
}

// ---------------- TF32 tensor-core GEMM (unchanged from round 2) ------------
__global__ void __launch_bounds__(256)
gemm_tf32(const float* __restrict__ X, const float* __restrict__ Wm,
          const float* __restrict__ bias, const float* __restrict__ res,
          float* __restrict__ Y, int O, int Cin, int act) {
    __shared__ uint32_t Ws[128][36];
    __shared__ uint32_t Xs[32][132];

    int b  = blockIdx.z;
    int o0 = blockIdx.y * 128;
    int n0 = blockIdx.x * 128;
    int tid  = threadIdx.x;
    int lane = tid & 31;
    int warp = tid >> 5;
    int wO = (warp >> 2) * 64;
    int wN = (warp & 3) * 32;
    const float* Xb = X + (size_t)b * Cin * Nn;

    float acc[4][4][4];
    #pragma unroll
    for (int m = 0; m < 4; m++)
        #pragma unroll
        for (int n = 0; n < 4; n++)
            #pragma unroll
            for (int r = 0; r < 4; r++) acc[m][n][r] = 0.f;

    for (int k0 = 0; k0 < Cin; k0 += 32) {
        #pragma unroll
        for (int r = 0; r < 4; r++) {
            int o  = (tid >> 3) + r * 32;
            int kk = (tid & 7) * 4;
            float4 w = *(const float4*)&Wm[(size_t)(o0 + o) * Cin + k0 + kk];
            uint4 u = make_uint4(f2tf32(w.x), f2tf32(w.y), f2tf32(w.z), f2tf32(w.w));
            *(uint4*)&Ws[o][kk] = u;
        }
        #pragma unroll
        for (int r = 0; r < 4; r++) {
            int kk = (tid >> 5) + r * 8;
            int nn = (tid & 31) * 4;
            float4 xv = *(const float4*)&Xb[(size_t)(k0 + kk) * Nn + n0 + nn];
            uint4 u = make_uint4(f2tf32(xv.x), f2tf32(xv.y), f2tf32(xv.z), f2tf32(xv.w));
            *(uint4*)&Xs[kk][nn] = u;
        }
        __syncthreads();

        #pragma unroll
        for (int ks = 0; ks < 4; ks++) {
            uint32_t af[4][4], bf[4][2];
            int rA = wO + (lane >> 2);
            int cA = ks * 8 + (lane & 3);
            #pragma unroll
            for (int m = 0; m < 4; m++) {
                int rr = rA + m * 16;
                af[m][0] = Ws[rr][cA];
                af[m][1] = Ws[rr + 8][cA];
                af[m][2] = Ws[rr][cA + 4];
                af[m][3] = Ws[rr + 8][cA + 4];
            }
            int kB = ks * 8 + (lane & 3);
            int nB = wN + (lane >> 2);
            #pragma unroll
            for (int n = 0; n < 4; n++) {
                bf[n][0] = Xs[kB][nB + n * 8];
                bf[n][1] = Xs[kB + 4][nB + n * 8];
            }
            #pragma unroll
            for (int m = 0; m < 4; m++)
                #pragma unroll
                for (int n = 0; n < 4; n++) {
                    asm volatile(
                        "mma.sync.aligned.m16n8k8.row.col.f32.tf32.tf32.f32 "
                        "{%0,%1,%2,%3}, {%4,%5,%6,%7}, {%8,%9}, {%0,%1,%2,%3};\n"
                        : "+f"(acc[m][n][0]), "+f"(acc[m][n][1]),
                          "+f"(acc[m][n][2]), "+f"(acc[m][n][3])
                        : "r"(af[m][0]), "r"(af[m][1]), "r"(af[m][2]), "r"(af[m][3]),
                          "r"(bf[n][0]), "r"(bf[n][1]));
                }
        }
        __syncthreads();
    }

    #pragma unroll
    for (int m = 0; m < 4; m++) {
        int row = o0 + wO + m * 16 + (lane >> 2);
        float bv0 = bias[row];
        float bv1 = bias[row + 8];
        #pragma unroll
        for (int n = 0; n < 4; n++) {
            int col = n0 + wN + n * 8 + 2 * (lane & 3);
            float t0 = acc[m][n][0] + bv0;
            float t1 = acc[m][n][1] + bv0;
            float t2 = acc[m][n][2] + bv1;
            float t3 = acc[m][n][3] + bv1;
            if (act) {
                t0 = 0.5f * t0 * (1.0f + erff(t0 * 0.70710678118654752f));
                t1 = 0.5f * t1 * (1.0f + erff(t1 * 0.70710678118654752f));
                t2 = 0.5f * t2 * (1.0f + erff(t2 * 0.70710678118654752f));
                t3 = 0.5f * t3 * (1.0f + erff(t3 * 0.70710678118654752f));
            }
            size_t off0 = ((size_t)b * O + row) * Nn + col;
            size_t off1 = ((size_t)b * O + row + 8) * Nn + col;
            if (res) {
                float2 r0 = *(const float2*)&res[off0];
                float2 r1 = *(const float2*)&res[off1];
                t0 += r0.x; t1 += r0.y; t2 += r1.x; t3 += r1.y;
            }
            *(float2*)&Y[off0] = make_float2(t0, t1);
            *(float2*)&Y[off1] = make_float2(t2, t3);
        }
    }
}

// ---------------- tensor-core flash attention -------------------------------
// grid (Nn/64, NHh, Bt), block 128 (4 warps). Warp w owns query rows w*16..+15.
// Key tiles of 64. S = (scale*log2e*Q)K^T via m16n8k8 tf32; online softmax in
// registers (base-2); P -> per-warp smem (tf32) -> PV mma.
#define PADK 72
#define PADV 49
#define PADP 68

__global__ void __launch_bounds__(128)
flash_tc(const float* __restrict__ qg, const float* __restrict__ kvg,
         const float* __restrict__ gbias, float* __restrict__ outg) {
    __shared__ uint32_t Ks[48][PADK];      // [d][j]
    __shared__ uint32_t Vs[64][PADV];      // [j][d] (transposed)
    __shared__ uint32_t Ps[4][16][PADP];   // per-warp P (tf32) / O (f32) staging
    __shared__ float    l_sh[64];

    int b = blockIdx.z, h = blockIdx.y, n0 = blockIdx.x * 64;
    int tid = threadIdx.x, lane = tid & 31, warp = tid >> 5;
    int wm = warp * 16;
    int qr = lane >> 2, qc = lane & 3;

    const float* Qb = qg  + ((size_t)b * MIDm + h * HDd) * Nn;
    const float* Kb = kvg + ((size_t)b * 2 * MIDm + h * HDd) * Nn;
    const float* Vb = kvg + ((size_t)b * 2 * MIDm + MIDm + h * HDd) * Nn;
    const float* Gb = gbias + ((size_t)h * Nn + n0 + wm) * Nn;

    const float qscale = 0.14433756729740645f * 1.4426950408889634f; // d^-1/2 * log2e

    // Q fragments in registers for the whole kernel (A of m16n8k8, row-major)
    uint32_t qa[6][4];
    #pragma unroll
    for (int ks = 0; ks < 6; ks++) {
        int d0 = ks * 8 + qc;
        qa[ks][0] = f2tf32(qscale * Qb[(size_t)d0 * Nn + n0 + wm + qr]);
        qa[ks][1] = f2tf32(qscale * Qb[(size_t)d0 * Nn + n0 + wm + 8 + qr]);
        qa[ks][2] = f2tf32(qscale * Qb[(size_t)(d0 + 4) * Nn + n0 + wm + qr]);
        qa[ks][3] = f2tf32(qscale * Qb[(size_t)(d0 + 4) * Nn + n0 + wm + 8 + qr]);
    }

    float oacc[6][4];
    #pragma unroll
    for (int nf = 0; nf < 6; nf++)
        #pragma unroll
        for (int r = 0; r < 4; r++) oacc[nf][r] = 0.f;
    float mr0 = -1e30f, mr1 = -1e30f, lr0 = 0.f, lr1 = 0.f;

    for (int t = 0; t < 16; t++) {
        int mm = t * 64;
        __syncthreads();
        for (int idx = tid; idx < 48 * 64; idx += 128) {
            int d = idx >> 6, j = idx & 63;
            Ks[d][j] = f2tf32(Kb[(size_t)d * Nn + mm + j]);
            Vs[j][d] = f2tf32(Vb[(size_t)d * Nn + mm + j]);
        }
        __syncthreads();

        // S = Q K^T  (16 x 64 per warp)
        float sacc[8][4];
        #pragma unroll
        for (int nf = 0; nf < 8; nf++)
            #pragma unroll
            for (int r = 0; r < 4; r++) sacc[nf][r] = 0.f;
        #pragma unroll
        for (int ks = 0; ks < 6; ks++) {
            #pragma unroll
            for (int nf = 0; nf < 8; nf++) {
                uint32_t b0 = Ks[ks * 8 + qc][nf * 8 + qr];
                uint32_t b1 = Ks[ks * 8 + qc + 4][nf * 8 + qr];
                asm volatile(
                    "mma.sync.aligned.m16n8k8.row.col.f32.tf32.tf32.f32 "
                    "{%0,%1,%2,%3}, {%4,%5,%6,%7}, {%8,%9}, {%0,%1,%2,%3};\n"
                    : "+f"(sacc[nf][0]), "+f"(sacc[nf][1]),
                      "+f"(sacc[nf][2]), "+f"(sacc[nf][3])
                    : "r"(qa[ks][0]), "r"(qa[ks][1]), "r"(qa[ks][2]), "r"(qa[ks][3]),
                      "r"(b0), "r"(b1));
            }
        }

        // + bias (already *log2e), coalesced float2 reads
        #pragma unroll
        for (int nf = 0; nf < 8; nf++) {
            int cb = mm + nf * 8 + 2 * qc;
            float2 b0 = *(const float2*)&Gb[(size_t)qr * Nn + cb];
            float2 b1 = *(const float2*)&Gb[(size_t)(qr + 8) * Nn + cb];
            sacc[nf][0] += b0.x; sacc[nf][1] += b0.y;
            sacc[nf][2] += b1.x; sacc[nf][3] += b1.y;
        }

        // online softmax (base-2). Rows qr and qr+8; cols spread over qc + frags.
        float ml0 = -1e30f, ml1 = -1e30f;
        #pragma unroll
        for (int nf = 0; nf < 8; nf++) {
            ml0 = fmaxf(ml0, fmaxf(sacc[nf][0], sacc[nf][1]));
            ml1 = fmaxf(ml1, fmaxf(sacc[nf][2], sacc[nf][3]));
        }
        ml0 = fmaxf(ml0, __shfl_xor_sync(0xffffffffu, ml0, 1));
        ml0 = fmaxf(ml0, __shfl_xor_sync(0xffffffffu, ml0, 2));
        ml1 = fmaxf(ml1, __shfl_xor_sync(0xffffffffu, ml1, 1));
        ml1 = fmaxf(ml1, __shfl_xor_sync(0xffffffffu, ml1, 2));
        float mn0 = fmaxf(mr0, ml0), mn1 = fmaxf(mr1, ml1);
        float al0 = exp2f(mr0 - mn0), al1 = exp2f(mr1 - mn1);
        float rs0 = 0.f, rs1 = 0.f;
        #pragma unroll
        for (int nf = 0; nf < 8; nf++) {
            sacc[nf][0] = exp2f(sacc[nf][0] - mn0);
            sacc[nf][1] = exp2f(sacc[nf][1] - mn0);
            sacc[nf][2] = exp2f(sacc[nf][2] - mn1);
            sacc[nf][3] = exp2f(sacc[nf][3] - mn1);
            rs0 += sacc[nf][0] + sacc[nf][1];
            rs1 += sacc[nf][2] + sacc[nf][3];
        }
        rs0 += __shfl_xor_sync(0xffffffffu, rs0, 1);
        rs0 += __shfl_xor_sync(0xffffffffu, rs0, 2);
        rs1 += __shfl_xor_sync(0xffffffffu, rs1, 1);
        rs1 += __shfl_xor_sync(0xffffffffu, rs1, 2);
        lr0 = lr0 * al0 + rs0;
        lr1 = lr1 * al1 + rs1;
        mr0 = mn0; mr1 = mn1;

        // P -> per-warp smem as tf32
        uint32_t* Pw = &Ps[warp][0][0];
        #pragma unroll
        for (int nf = 0; nf < 8; nf++) {
            int cb = nf * 8 + 2 * qc;
            *(uint2*)&Pw[qr * PADP + cb] =
                make_uint2(f2tf32(sacc[nf][0]), f2tf32(sacc[nf][1]));
            *(uint2*)&Pw[(qr + 8) * PADP + cb] =
                make_uint2(f2tf32(sacc[nf][2]), f2tf32(sacc[nf][3]));
        }
        __syncwarp();

        // rescale O
        #pragma unroll
        for (int nf = 0; nf < 6; nf++) {
            oacc[nf][0] *= al0; oacc[nf][1] *= al0;
            oacc[nf][2] *= al1; oacc[nf][3] *= al1;
        }

        // O += P V  (16 x 48 per warp, K = 64 keys)
        #pragma unroll
        for (int ks = 0; ks < 8; ks++) {
            uint32_t pa0 = Pw[qr * PADP + ks * 8 + qc];
            uint32_t pa1 = Pw[(qr + 8) * PADP + ks * 8 + qc];
            uint32_t pa2 = Pw[qr * PADP + ks * 8 + qc + 4];
            uint32_t pa3 = Pw[(qr + 8) * PADP + ks * 8 + qc + 4];
            #pragma unroll
            for (int nf = 0; nf < 6; nf++) {
                uint32_t b0 = Vs[ks * 8 + qc][nf * 8 + qr];
                uint32_t b1 = Vs[ks * 8 + qc + 4][nf * 8 + qr];
                asm volatile(
                    "mma.sync.aligned.m16n8k8.row.col.f32.tf32.tf32.f32 "
                    "{%0,%1,%2,%3}, {%4,%5,%6,%7}, {%8,%9}, {%0,%1,%2,%3};\n"
                    : "+f"(oacc[nf][0]), "+f"(oacc[nf][1]),
                      "+f"(oacc[nf][2]), "+f"(oacc[nf][3])
                    : "r"(pa0), "r"(pa1), "r"(pa2), "r"(pa3),
                      "r"(b0), "r"(b1));
            }
        }
    }

    // epilogue: 1/l, stage O in smem, write coalesced [MID, N]
    if (qc == 0) {
        l_sh[wm + qr]     = 1.0f / lr0;
        l_sh[wm + 8 + qr] = 1.0f / lr1;
    }
    float* Pf = (float*)&Ps[warp][0][0];
    #pragma unroll
    for (int nf = 0; nf < 6; nf++) {
        int cb = nf * 8 + 2 * qc;
        *(float2*)&Pf[qr * PADP + cb]       = make_float2(oacc[nf][0], oacc[nf][1]);
        *(float2*)&Pf[(qr + 8) * PADP + cb] = make_float2(oacc[nf][2], oacc[nf][3]);
    }
    __syncwarp();
    float* outb = outg + ((size_t)b * MIDm + h * HDd) * Nn + n0 + wm;
    for (int idx = lane; idx < 16 * 48; idx += 32) {
        int rr = idx & 15, d = idx >> 4;
        outb[(size_t)d * Nn + rr] = Pf[rr * PADP + d] * l_sh[wm + rr];
    }
}

// ---------------- launch --------------------------------------------------
extern "C" void kernel_launch(void* const* d_in, const int* in_sizes, int n_in,
                              void* d_out, int out_size) {
    const float* x     = (const float*)d_in[0];
    const float* rpb   = (const float*)d_in[1];
    const int*   ridx  = (const int*)  d_in[2];
    const float* ln1g  = (const float*)d_in[3];
    const float* ln1b  = (const float*)d_in[4];
    const float* ln2g  = (const float*)d_in[5];
    const float* ln2b  = (const float*)d_in[6];
    const float* wq    = (const float*)d_in[7];
    const float* bq    = (const float*)d_in[8];
    const float* wkv   = (const float*)d_in[9];
    const float* bkv   = (const float*)d_in[10];
    const float* wproj = (const float*)d_in[11];
    const float* bproj = (const float*)d_in[12];
    const float* w1    = (const float*)d_in[13];
    const float* b1    = (const float*)d_in[14];
    const float* w2    = (const float*)d_in[15];
    const float* b2    = (const float*)d_in[16];
    float* out = (float*)d_out;

    float *h1, *q, *kv, *att, *x2, *h2, *hid, *gb;
    cudaGetSymbolAddress((void**)&h1,  g_h1);
    cudaGetSymbolAddress((void**)&q,   g_q);
    cudaGetSymbolAddress((void**)&kv,  g_kv);
    cudaGetSymbolAddress((void**)&att, g_att);
    cudaGetSymbolAddress((void**)&x2,  g_x2);
    cudaGetSymbolAddress((void**)&h2,  g_h2);
    cudaGetSymbolAddress((void**)&hid, g_hid);
    cudaGetSymbolAddress((void**)&gb,  g_bias);

    dim3 lnGrid(Nn / 32, Bt), lnBlk(32, 8);

    // bias precompute + LN1
    bias_pre<<<Nn * Nn / 256, 256>>>(rpb, ridx, gb);
    ln_kernel<<<lnGrid, lnBlk>>>(x, ln1g, ln1b, h1);
    // Q / KV projections (tensor cores, tf32)
    gemm_tf32<<<dim3(Nn / 128, MIDm / 128, Bt), 256>>>(h1, wq, bq, nullptr, q, MIDm, Cc, 0);
    gemm_tf32<<<dim3(Nn / 128, 2 * MIDm / 128, Bt), 256>>>(h1, wkv, bkv, nullptr, kv, 2 * MIDm, Cc, 0);
    // attention (tensor cores)
    flash_tc<<<dim3(Nn / 64, NHh, Bt), 128>>>(q, kv, gb, att);
    // output projection + residual
    gemm_tf32<<<dim3(Nn / 128, Cc / 128, Bt), 256>>>(att, wproj, bproj, x, x2, Cc, MIDm, 0);
    // LN2
    ln_kernel<<<lnGrid, lnBlk>>>(x2, ln2g, ln2b, h2);
    // MLP
    gemm_tf32<<<dim3(Nn / 128, HIDh / 128, Bt), 256>>>(h2, w1, b1, nullptr, hid, HIDh, Cc, 1);
    gemm_tf32<<<dim3(Nn / 128, Cc / 128, Bt), 256>>>(hid, w2, b2, x2, out, Cc, HIDh, 0);
}

// round 4
// speedup vs baseline: 2.7116x; 1.0006x over previous
#include <cuda_runtime.h>
#include <math.h>
#include <stdint.h>

#define Bt   16
#define Cc   384
#define Nn   1024
#define NHh  8
#define HDd  48
#define MIDm 384
#define HIDh 1536

// ---------------- scratch (device globals; no allocations allowed) ----------
__device__ float g_h1  [Bt * Cc   * Nn];
__device__ float g_q   [Bt * MIDm * Nn];
__device__ float g_kv  [Bt * 2 * MIDm * Nn];
__device__ float g_att [Bt * MIDm * Nn];
__device__ float g_x2  [Bt * Cc   * Nn];
__device__ float g_h2  [Bt * Cc   * Nn];
__device__ float g_hid [Bt * HIDh * Nn];
__device__ float g_bias[NHh * Nn * Nn];   // 32 MB precomputed softmax bias (*log2e)

__device__ __forceinline__ uint32_t f2tf32(float f) {
    uint32_t u;
    asm("cvt.rna.tf32.f32 %0, %1;" : "=r"(u) : "f"(f));
    return u;
}

// ---------------- bias precompute: gbias[h][n][m] = rpb[ridx[n][m]][h]*log2e -
__global__ void bias_pre(const float* __restrict__ rpb, const int* __restrict__ ridx,
                         float* __restrict__ gb) {
    int idx = blockIdx.x * 256 + threadIdx.x;          // over Nn*Nn
    int r = ridx[idx];
    float4 t0 = *(const float4*)&rpb[r * NHh];
    float4 t1 = *(const float4*)&rpb[r * NHh + 4];
    const float L2E = 1.4426950408889634f;
    gb[0 * Nn * Nn + idx] = t0.x * L2E;
    gb[1 * Nn * Nn + idx] = t0.y * L2E;
    gb[2 * Nn * Nn + idx] = t0.z * L2E;
    gb[3 * Nn * Nn + idx] = t0.w * L2E;
    gb[4 * Nn * Nn + idx] = t1.x * L2E;
    gb[5 * Nn * Nn + idx] = t1.y * L2E;
    gb[6 * Nn * Nn + idx] = t1.z * L2E;
    gb[7 * Nn * Nn + idx] = t1.w * L2E;
}

// ---------------- channel LayerNorm over NCHW (per (b, spatial)) ------------
__global__ void ln_kernel(const float* __restrict__ X,
                          const float* __restrict__ gam,
                          const float* __restrict__ bet,
                          float* __restrict__ Y) {
    __shared__ float ss[8][32], sq[8][32], sm[32], sr[32];
    int b  = blockIdx.y;
    int n  = blockIdx.x * 32 + threadIdx.x;
    int ty = threadIdx.y;
    const float* xb = X + (size_t)b * Cc * Nn + n;
    float s = 0.f, q = 0.f;
    for (int c = ty; c < Cc; c += 8) {
        float v = xb[(size_t)c * Nn];
        s += v; q += v * v;
    }
    ss[ty][threadIdx.x] = s;
    sq[ty][threadIdx.x] = q;
    __syncthreads();
    if (ty == 0) {
        float S = 0.f, Q = 0.f;
        #pragma unroll
        for (int r = 0; r < 8; r++) { S += ss[r][threadIdx.x]; Q += sq[r][threadIdx.x]; }
        float mean = S * (1.0f / Cc);
        float var  = Q * (1.0f / Cc) - mean * mean;
        sm[threadIdx.x] = mean;
        sr[threadIdx.x] = rsqrtf(var + 1e-5f);
    }
    __syncthreads();
    float mean = sm[threadIdx.x];
    float rstd = sr[threadIdx.x];
    float* yb = Y + (size_t)b * Cc * Nn + n;
    for (int c = ty; c < Cc; c += 8) {
        float v = xb[(size_t)c * Nn];
        yb[(size_t)c * Nn] = (v - mean) * rstd * gam[c] + bet[c];
    }
}

// ---------------- TF32 tensor-core GEMM (unchanged from round 2) ------------
__global__ void __launch_bounds__(256)
gemm_tf32(const float* __restrict__ X, const float* __restrict__ Wm,
          const float* __restrict__ bias, const float* __restrict__ res,
          float* __restrict__ Y, int O, int Cin, int act) {
    __shared__ uint32_t Ws[128][36];
    __shared__ uint32_t Xs[32][132];

    int b  = blockIdx.z;
    int o0 = blockIdx.y * 128;
    int n0 = blockIdx.x * 128;
    int tid  = threadIdx.x;
    int lane = tid & 31;
    int warp = tid >> 5;
    int wO = (warp >> 2) * 64;
    int wN = (warp & 3) * 32;
    const float* Xb = X + (size_t)b * Cin * Nn;

    float acc[4][4][4];
    #pragma unroll
    for (int m = 0; m < 4; m++)
        #pragma unroll
        for (int n = 0; n < 4; n++)
            #pragma unroll
            for (int r = 0; r < 4; r++) acc[m][n][r] = 0.f;

    for (int k0 = 0; k0 < Cin; k0 += 32) {
        #pragma unroll
        for (int r = 0; r < 4; r++) {
            int o  = (tid >> 3) + r * 32;
            int kk = (tid & 7) * 4;
            float4 w = *(const float4*)&Wm[(size_t)(o0 + o) * Cin + k0 + kk];
            uint4 u = make_uint4(f2tf32(w.x), f2tf32(w.y), f2tf32(w.z), f2tf32(w.w));
            *(uint4*)&Ws[o][kk] = u;
        }
        #pragma unroll
        for (int r = 0; r < 4; r++) {
            int kk = (tid >> 5) + r * 8;
            int nn = (tid & 31) * 4;
            float4 xv = *(const float4*)&Xb[(size_t)(k0 + kk) * Nn + n0 + nn];
            uint4 u = make_uint4(f2tf32(xv.x), f2tf32(xv.y), f2tf32(xv.z), f2tf32(xv.w));
            *(uint4*)&Xs[kk][nn] = u;
        }
        __syncthreads();

        #pragma unroll
        for (int ks = 0; ks < 4; ks++) {
            uint32_t af[4][4], bf[4][2];
            int rA = wO + (lane >> 2);
            int cA = ks * 8 + (lane & 3);
            #pragma unroll
            for (int m = 0; m < 4; m++) {
                int rr = rA + m * 16;
                af[m][0] = Ws[rr][cA];
                af[m][1] = Ws[rr + 8][cA];
                af[m][2] = Ws[rr][cA + 4];
                af[m][3] = Ws[rr + 8][cA + 4];
            }
            int kB = ks * 8 + (lane & 3);
            int nB = wN + (lane >> 2);
            #pragma unroll
            for (int n = 0; n < 4; n++) {
                bf[n][0] = Xs[kB][nB + n * 8];
                bf[n][1] = Xs[kB + 4][nB + n * 8];
            }
            #pragma unroll
            for (int m = 0; m < 4; m++)
                #pragma unroll
                for (int n = 0; n < 4; n++) {
                    asm volatile(
                        "mma.sync.aligned.m16n8k8.row.col.f32.tf32.tf32.f32 "
                        "{%0,%1,%2,%3}, {%4,%5,%6,%7}, {%8,%9}, {%0,%1,%2,%3};\n"
                        : "+f"(acc[m][n][0]), "+f"(acc[m][n][1]),
                          "+f"(acc[m][n][2]), "+f"(acc[m][n][3])
                        : "r"(af[m][0]), "r"(af[m][1]), "r"(af[m][2]), "r"(af[m][3]),
                          "r"(bf[n][0]), "r"(bf[n][1]));
                }
        }
        __syncthreads();
    }

    #pragma unroll
    for (int m = 0; m < 4; m++) {
        int row = o0 + wO + m * 16 + (lane >> 2);
        float bv0 = bias[row];
        float bv1 = bias[row + 8];
        #pragma unroll
        for (int n = 0; n < 4; n++) {
            int col = n0 + wN + n * 8 + 2 * (lane & 3);
            float t0 = acc[m][n][0] + bv0;
            float t1 = acc[m][n][1] + bv0;
            float t2 = acc[m][n][2] + bv1;
            float t3 = acc[m][n][3] + bv1;
            if (act) {
                t0 = 0.5f * t0 * (1.0f + erff(t0 * 0.70710678118654752f));
                t1 = 0.5f * t1 * (1.0f + erff(t1 * 0.70710678118654752f));
                t2 = 0.5f * t2 * (1.0f + erff(t2 * 0.70710678118654752f));
                t3 = 0.5f * t3 * (1.0f + erff(t3 * 0.70710678118654752f));
            }
            size_t off0 = ((size_t)b * O + row) * Nn + col;
            size_t off1 = ((size_t)b * O + row + 8) * Nn + col;
            if (res) {
                float2 r0 = *(const float2*)&res[off0];
                float2 r1 = *(const float2*)&res[off1];
                t0 += r0.x; t1 += r0.y; t2 += r1.x; t3 += r1.y;
            }
            *(float2*)&Y[off0] = make_float2(t0, t1);
            *(float2*)&Y[off1] = make_float2(t2, t3);
        }
    }
}

// ---------------- tensor-core flash attention -------------------------------
// grid (Nn/64, NHh, Bt), block 128 (4 warps). Warp w owns query rows w*16..+15.
// Key tiles of 64. S = (scale*log2e*Q)K^T via m16n8k8 tf32; online softmax in
// registers (base-2); P -> per-warp smem (tf32) -> PV mma.
#define PADK 72
#define PADV 49
#define PADP 68

__global__ void __launch_bounds__(128)
flash_tc(const float* __restrict__ qg, const float* __restrict__ kvg,
         const float* __restrict__ gbias, float* __restrict__ outg) {
    __shared__ uint32_t Ks[48][PADK];      // [d][j]
    __shared__ uint32_t Vs[64][PADV];      // [j][d] (transposed)
    __shared__ uint32_t Ps[4][16][PADP];   // per-warp P (tf32) / O (f32) staging
    __shared__ float    l_sh[64];

    int b = blockIdx.z, h = blockIdx.y, n0 = blockIdx.x * 64;
    int tid = threadIdx.x, lane = tid & 31, warp = tid >> 5;
    int wm = warp * 16;
    int qr = lane >> 2, qc = lane & 3;

    const float* Qb = qg  + ((size_t)b * MIDm + h * HDd) * Nn;
    const float* Kb = kvg + ((size_t)b * 2 * MIDm + h * HDd) * Nn;
    const float* Vb = kvg + ((size_t)b * 2 * MIDm + MIDm + h * HDd) * Nn;
    const float* Gb = gbias + ((size_t)h * Nn + n0 + wm) * Nn;

    const float qscale = 0.14433756729740645f * 1.4426950408889634f; // d^-1/2 * log2e

    // Q fragments in registers for the whole kernel (A of m16n8k8, row-major)
    uint32_t qa[6][4];
    #pragma unroll
    for (int ks = 0; ks < 6; ks++) {
        int d0 = ks * 8 + qc;
        qa[ks][0] = f2tf32(qscale * Qb[(size_t)d0 * Nn + n0 + wm + qr]);
        qa[ks][1] = f2tf32(qscale * Qb[(size_t)d0 * Nn + n0 + wm + 8 + qr]);
        qa[ks][2] = f2tf32(qscale * Qb[(size_t)(d0 + 4) * Nn + n0 + wm + qr]);
        qa[ks][3] = f2tf32(qscale * Qb[(size_t)(d0 + 4) * Nn + n0 + wm + 8 + qr]);
    }

    float oacc[6][4];
    #pragma unroll
    for (int nf = 0; nf < 6; nf++)
        #pragma unroll
        for (int r = 0; r < 4; r++) oacc[nf][r] = 0.f;
    float mr0 = -1e30f, mr1 = -1e30f, lr0 = 0.f, lr1 = 0.f;

    for (int t = 0; t < 16; t++) {
        int mm = t * 64;
        __syncthreads();
        for (int idx = tid; idx < 48 * 64; idx += 128) {
            int d = idx >> 6, j = idx & 63;
            Ks[d][j] = f2tf32(Kb[(size_t)d * Nn + mm + j]);
            Vs[j][d] = f2tf32(Vb[(size_t)d * Nn + mm + j]);
        }
        __syncthreads();

        // S = Q K^T  (16 x 64 per warp)
        float sacc[8][4];
        #pragma unroll
        for (int nf = 0; nf < 8; nf++)
            #pragma unroll
            for (int r = 0; r < 4; r++) sacc[nf][r] = 0.f;
        #pragma unroll
        for (int ks = 0; ks < 6; ks++) {
            #pragma unroll
            for (int nf = 0; nf < 8; nf++) {
                uint32_t b0 = Ks[ks * 8 + qc][nf * 8 + qr];
                uint32_t b1 = Ks[ks * 8 + qc + 4][nf * 8 + qr];
                asm volatile(
                    "mma.sync.aligned.m16n8k8.row.col.f32.tf32.tf32.f32 "
                    "{%0,%1,%2,%3}, {%4,%5,%6,%7}, {%8,%9}, {%0,%1,%2,%3};\n"
                    : "+f"(sacc[nf][0]), "+f"(sacc[nf][1]),
                      "+f"(sacc[nf][2]), "+f"(sacc[nf][3])
                    : "r"(qa[ks][0]), "r"(qa[ks][1]), "r"(qa[ks][2]), "r"(qa[ks][3]),
                      "r"(b0), "r"(b1));
            }
        }

        // + bias (already *log2e), coalesced float2 reads
        #pragma unroll
        for (int nf = 0; nf < 8; nf++) {
            int cb = mm + nf * 8 + 2 * qc;
            float2 b0 = *(const float2*)&Gb[(size_t)qr * Nn + cb];
            float2 b1 = *(const float2*)&Gb[(size_t)(qr + 8) * Nn + cb];
            sacc[nf][0] += b0.x; sacc[nf][1] += b0.y;
            sacc[nf][2] += b1.x; sacc[nf][3] += b1.y;
        }

        // online softmax (base-2). Rows qr and qr+8; cols spread over qc + frags.
        float ml0 = -1e30f, ml1 = -1e30f;
        #pragma unroll
        for (int nf = 0; nf < 8; nf++) {
            ml0 = fmaxf(ml0, fmaxf(sacc[nf][0], sacc[nf][1]));
            ml1 = fmaxf(ml1, fmaxf(sacc[nf][2], sacc[nf][3]));
        }
        ml0 = fmaxf(ml0, __shfl_xor_sync(0xffffffffu, ml0, 1));
        ml0 = fmaxf(ml0, __shfl_xor_sync(0xffffffffu, ml0, 2));
        ml1 = fmaxf(ml1, __shfl_xor_sync(0xffffffffu, ml1, 1));
        ml1 = fmaxf(ml1, __shfl_xor_sync(0xffffffffu, ml1, 2));
        float mn0 = fmaxf(mr0, ml0), mn1 = fmaxf(mr1, ml1);
        float al0 = exp2f(mr0 - mn0), al1 = exp2f(mr1 - mn1);
        float rs0 = 0.f, rs1 = 0.f;
        #pragma unroll
        for (int nf = 0; nf < 8; nf++) {
            sacc[nf][0] = exp2f(sacc[nf][0] - mn0);
            sacc[nf][1] = exp2f(sacc[nf][1] - mn0);
            sacc[nf][2] = exp2f(sacc[nf][2] - mn1);
            sacc[nf][3] = exp2f(sacc[nf][3] - mn1);
            rs0 += sacc[nf][0] + sacc[nf][1];
            rs1 += sacc[nf][2] + sacc[nf][3];
        }
        rs0 += __shfl_xor_sync(0xffffffffu, rs0, 1);
        rs0 += __shfl_xor_sync(0xffffffffu, rs0, 2);
        rs1 += __shfl_xor_sync(0xffffffffu, rs1, 1);
        rs1 += __shfl_xor_sync(0xffffffffu, rs1, 2);
        lr0 = lr0 * al0 + rs0;
        lr1 = lr1 * al1 + rs1;
        mr0 = mn0; mr1 = mn1;

        // P -> per-warp smem as tf32
        uint32_t* Pw = &Ps[warp][0][0];
        #pragma unroll
        for (int nf = 0; nf < 8; nf++) {
            int cb = nf * 8 + 2 * qc;
            *(uint2*)&Pw[qr * PADP + cb] =
                make_uint2(f2tf32(sacc[nf][0]), f2tf32(sacc[nf][1]));
            *(uint2*)&Pw[(qr + 8) * PADP + cb] =
                make_uint2(f2tf32(sacc[nf][2]), f2tf32(sacc[nf][3]));
        }
        __syncwarp();

        // rescale O
        #pragma unroll
        for (int nf = 0; nf < 6; nf++) {
            oacc[nf][0] *= al0; oacc[nf][1] *= al0;
            oacc[nf][2] *= al1; oacc[nf][3] *= al1;
        }

        // O += P V  (16 x 48 per warp, K = 64 keys)
        #pragma unroll
        for (int ks = 0; ks < 8; ks++) {
            uint32_t pa0 = Pw[qr * PADP + ks * 8 + qc];
            uint32_t pa1 = Pw[(qr + 8) * PADP + ks * 8 + qc];
            uint32_t pa2 = Pw[qr * PADP + ks * 8 + qc + 4];
            uint32_t pa3 = Pw[(qr + 8) * PADP + ks * 8 + qc + 4];
            #pragma unroll
            for (int nf = 0; nf < 6; nf++) {
                uint32_t b0 = Vs[ks * 8 + qc][nf * 8 + qr];
                uint32_t b1 = Vs[ks * 8 + qc + 4][nf * 8 + qr];
                asm volatile(
                    "mma.sync.aligned.m16n8k8.row.col.f32.tf32.tf32.f32 "
                    "{%0,%1,%2,%3}, {%4,%5,%6,%7}, {%8,%9}, {%0,%1,%2,%3};\n"
                    : "+f"(oacc[nf][0]), "+f"(oacc[nf][1]),
                      "+f"(oacc[nf][2]), "+f"(oacc[nf][3])
                    : "r"(pa0), "r"(pa1), "r"(pa2), "r"(pa3),
                      "r"(b0), "r"(b1));
            }
        }
    }

    // epilogue: 1/l, stage O in smem, write coalesced [MID, N]
    if (qc == 0) {
        l_sh[wm + qr]     = 1.0f / lr0;
        l_sh[wm + 8 + qr] = 1.0f / lr1;
    }
    float* Pf = (float*)&Ps[warp][0][0];
    #pragma unroll
    for (int nf = 0; nf < 6; nf++) {
        int cb = nf * 8 + 2 * qc;
        *(float2*)&Pf[qr * PADP + cb]       = make_float2(oacc[nf][0], oacc[nf][1]);
        *(float2*)&Pf[(qr + 8) * PADP + cb] = make_float2(oacc[nf][2], oacc[nf][3]);
    }
    __syncwarp();
    float* outb = outg + ((size_t)b * MIDm + h * HDd) * Nn + n0 + wm;
    for (int idx = lane; idx < 16 * 48; idx += 32) {
        int rr = idx & 15, d = idx >> 4;
        outb[(size_t)d * Nn + rr] = Pf[rr * PADP + d] * l_sh[wm + rr];
    }
}

// ---------------- launch --------------------------------------------------
extern "C" void kernel_launch(void* const* d_in, const int* in_sizes, int n_in,
                              void* d_out, int out_size) {
    const float* x     = (const float*)d_in[0];
    const float* rpb   = (const float*)d_in[1];
    const int*   ridx  = (const int*)  d_in[2];
    const float* ln1g  = (const float*)d_in[3];
    const float* ln1b  = (const float*)d_in[4];
    const float* ln2g  = (const float*)d_in[5];
    const float* ln2b  = (const float*)d_in[6];
    const float* wq    = (const float*)d_in[7];
    const float* bq    = (const float*)d_in[8];
    const float* wkv   = (const float*)d_in[9];
    const float* bkv   = (const float*)d_in[10];
    const float* wproj = (const float*)d_in[11];
    const float* bproj = (const float*)d_in[12];
    const float* w1    = (const float*)d_in[13];
    const float* b1    = (const float*)d_in[14];
    const float* w2    = (const float*)d_in[15];
    const float* b2    = (const float*)d_in[16];
    float* out = (float*)d_out;

    float *h1, *q, *kv, *att, *x2, *h2, *hid, *gb;
    cudaGetSymbolAddress((void**)&h1,  g_h1);
    cudaGetSymbolAddress((void**)&q,   g_q);
    cudaGetSymbolAddress((void**)&kv,  g_kv);
    cudaGetSymbolAddress((void**)&att, g_att);
    cudaGetSymbolAddress((void**)&x2,  g_x2);
    cudaGetSymbolAddress((void**)&h2,  g_h2);
    cudaGetSymbolAddress((void**)&hid, g_hid);
    cudaGetSymbolAddress((void**)&gb,  g_bias);

    dim3 lnGrid(Nn / 32, Bt), lnBlk(32, 8);

    // bias precompute + LN1
    bias_pre<<<Nn * Nn / 256, 256>>>(rpb, ridx, gb);
    ln_kernel<<<lnGrid, lnBlk>>>(x, ln1g, ln1b, h1);
    // Q / KV projections (tensor cores, tf32)
    gemm_tf32<<<dim3(Nn / 128, MIDm / 128, Bt), 256>>>(h1, wq, bq, nullptr, q, MIDm, Cc, 0);
    gemm_tf32<<<dim3(Nn / 128, 2 * MIDm / 128, Bt), 256>>>(h1, wkv, bkv, nullptr, kv, 2 * MIDm, Cc, 0);
    // attention (tensor cores)
    flash_tc<<<dim3(Nn / 64, NHh, Bt), 128>>>(q, kv, gb, att);
    // output projection + residual
    gemm_tf32<<<dim3(Nn / 128, Cc / 128, Bt), 256>>>(att, wproj, bproj, x, x2, Cc, MIDm, 0);
    // LN2
    ln_kernel<<<lnGrid, lnBlk>>>(x2, ln2g, ln2b, h2);
    // MLP
    gemm_tf32<<<dim3(Nn / 128, HIDh / 128, Bt), 256>>>(h2, w1, b1, nullptr, hid, HIDh, Cc, 1);
    gemm_tf32<<<dim3(Nn / 128, Cc / 128, Bt), 256>>>(hid, w2, b2, x2, out, Cc, HIDh, 0);
}